// round 16
// baseline (speedup 1.0000x reference)
#include <cuda_runtime.h>
#include <math.h>
#include <stdint.h>

#define B_ 4
#define S_ 1024
#define D_ 512
#define H_ 8
#define E_ 64
#define BS_ (B_*S_)

// Scratch (device globals — no runtime allocation allowed)
__device__ float g_Q[H_*BS_*E_];     // [H][B*S][E]
__device__ float g_K[H_*BS_*E_];
__device__ float g_V[BS_*E_];
__device__ float g_M[BS_*E_];        // mean-over-heads accumulator
__device__ float g_G[B_*128*D_];     // final-GEMM output [512][512]

// ---------------------------------------------------------------------------
__device__ __forceinline__ uint32_t f2tf32(float x) {
    uint32_t r;
    asm("cvt.rna.tf32.f32 %0, %1;" : "=r"(r) : "f"(x));
    return r;
}
__device__ __forceinline__ uint4 f2tf32_v4(float4 v) {
    return make_uint4(f2tf32(v.x), f2tf32(v.y), f2tf32(v.z), f2tf32(v.w));
}

// D += A(16x8,row) * B(8x8,col)   tf32, fp32 accum
__device__ __forceinline__ void mma_tf32(float c[4],
                                         uint32_t a0, uint32_t a1, uint32_t a2, uint32_t a3,
                                         uint32_t b0, uint32_t b1) {
    asm volatile(
        "mma.sync.aligned.m16n8k8.row.col.f32.tf32.tf32.f32 "
        "{%0,%1,%2,%3}, {%4,%5,%6,%7}, {%8,%9}, {%0,%1,%2,%3};\n"
        : "+f"(c[0]), "+f"(c[1]), "+f"(c[2]), "+f"(c[3])
        : "r"(a0), "r"(a1), "r"(a2), "r"(a3), "r"(b0), "r"(b1));
}

// ---------------------------------------------------------------------------
__global__ void zero_m_kernel() {
    int i = blockIdx.x * blockDim.x + threadIdx.x;
    int stride = gridDim.x * blockDim.x;
    for (; i < BS_*E_; i += stride) g_M[i] = 0.f;
}

// ---------------------------------------------------------------------------
// Batched projections, single-pass tf32, vectorized STS.128 converts,
// register prefetch. p<8: Q head p; p<16: K; 16: V.
__global__ void proj_mma_kernel(const float* __restrict__ q, const float* __restrict__ k,
                                const float* __restrict__ v,
                                const float* __restrict__ Wq, const float* __restrict__ bq,
                                const float* __restrict__ Wk, const float* __restrict__ bk,
                                const float* __restrict__ Wv, const float* __restrict__ bv) {
    const int p = blockIdx.y;
    const float* A; const float* W; const float* bias; float* out;
    if (p < 8)       { A = q; W = Wq + (size_t)p*D_*E_;     bias = bq + p*E_;     out = g_Q + (size_t)p*BS_*E_; }
    else if (p < 16) { A = k; W = Wk + (size_t)(p-8)*D_*E_; bias = bk + (p-8)*E_; out = g_K + (size_t)(p-8)*BS_*E_; }
    else             { A = v; W = Wv;                        bias = bv;            out = g_V; }

    __shared__ uint32_t As[64*36];   // [row][k]  tf32 bits
    __shared__ uint32_t Bs[32*68];   // [k][n]    tf32 bits

    const int tid  = threadIdx.x;
    const int lane = tid & 31;
    const int warp = tid >> 5;
    const int wm = warp >> 1, wn = warp & 1;
    const int grp = lane >> 2, qid = lane & 3;
    const int m0 = blockIdx.x * 64;

    const int ar[4] = { (tid      ) >> 3, (tid + 128) >> 3, (tid + 256) >> 3, (tid + 384) >> 3 };
    const int ac[4] = { ((tid      ) & 7)*4, ((tid + 128) & 7)*4, ((tid + 256) & 7)*4, ((tid + 384) & 7)*4 };
    const int br[4] = { (tid      ) >> 4, (tid + 128) >> 4, (tid + 256) >> 4, (tid + 384) >> 4 };
    const int bc[4] = { ((tid      ) & 15)*4, ((tid + 128) & 15)*4, ((tid + 256) & 15)*4, ((tid + 384) & 15)*4 };

    float4 a_pre[4], b_pre[4];
    #pragma unroll
    for (int t = 0; t < 4; t++) {
        a_pre[t] = *(const float4*)&A[(size_t)(m0 + ar[t])*D_ + ac[t]];
        b_pre[t] = *(const float4*)&W[(size_t)br[t]*E_ + bc[t]];
    }

    float acc[2][4][4] = {};

    for (int k0 = 0; k0 < D_; k0 += 32) {
        #pragma unroll
        for (int t = 0; t < 4; t++) {
            *(uint4*)&As[ar[t]*36 + ac[t]] = f2tf32_v4(a_pre[t]);
            *(uint4*)&Bs[br[t]*68 + bc[t]] = f2tf32_v4(b_pre[t]);
        }
        if (k0 + 32 < D_) {
            #pragma unroll
            for (int t = 0; t < 4; t++) {
                a_pre[t] = *(const float4*)&A[(size_t)(m0 + ar[t])*D_ + k0 + 32 + ac[t]];
                b_pre[t] = *(const float4*)&W[(size_t)(k0 + 32 + br[t])*E_ + bc[t]];
            }
        }
        __syncthreads();

        #pragma unroll
        for (int ks = 0; ks < 4; ks++) {
            uint32_t a[2][4];
            #pragma unroll
            for (int i = 0; i < 2; i++) {
                int row = wm*32 + i*16;
                a[i][0] = As[(row+grp  )*36 + ks*8 + qid    ];
                a[i][1] = As[(row+grp+8)*36 + ks*8 + qid    ];
                a[i][2] = As[(row+grp  )*36 + ks*8 + qid + 4];
                a[i][3] = As[(row+grp+8)*36 + ks*8 + qid + 4];
            }
            #pragma unroll
            for (int j = 0; j < 4; j++) {
                int col = wn*32 + j*8;
                uint32_t b0 = Bs[(ks*8 + qid    )*68 + col + grp];
                uint32_t b1 = Bs[(ks*8 + qid + 4)*68 + col + grp];
                mma_tf32(acc[0][j], a[0][0], a[0][1], a[0][2], a[0][3], b0, b1);
                mma_tf32(acc[1][j], a[1][0], a[1][1], a[1][2], a[1][3], b0, b1);
            }
        }
        __syncthreads();
    }

    #pragma unroll
    for (int i = 0; i < 2; i++) {
        int row0 = m0 + wm*32 + i*16 + grp;
        #pragma unroll
        for (int j = 0; j < 4; j++) {
            int col0 = wn*32 + j*8 + qid*2;
            out[(size_t)row0*E_     + col0    ] = acc[i][j][0] + bias[col0    ];
            out[(size_t)row0*E_     + col0 + 1] = acc[i][j][1] + bias[col0 + 1];
            out[(size_t)(row0+8)*E_ + col0    ] = acc[i][j][2] + bias[col0    ];
            out[(size_t)(row0+8)*E_ + col0 + 1] = acc[i][j][3] + bias[col0 + 1];
        }
    }
}

// ---------------------------------------------------------------------------
// Full-MMA flash attention, all single-pass tf32 (R15) with:
//  - heavy-tiles-first scheduling (qt reversed)
//  - vectorized STS.128 for Q/V converts, STS.64 score stores,
//    LDS.128/STS.128 in softmax.
__global__ void attn_kernel() {
    const int qt = (int)gridDim.x - 1 - (int)blockIdx.x;   // heavy first
    const int b = blockIdx.y, h = blockIdx.z;
    extern __shared__ float sm[];
    uint32_t* QsU = (uint32_t*)sm;           // 64*68 [q][e]   tf32 bits
    uint32_t* KtU = QsU + 64*68;             // 64*68 [e][key] tf32 bits
    uint32_t* VsU = KtU + 64*68;             // 64*68 [key][e] tf32 bits
    float*    Ss  = (float*)(VsU + 64*68);   // 64*68 scores fp32 -> P tf32 bits
    uint32_t* SsU = (uint32_t*)Ss;
    float* m_sh = Ss + 64*68;
    float* l_sh = m_sh + 64;
    float* c_sh = l_sh + 64;

    const int tid  = threadIdx.x;
    const int lane = tid & 31;
    const int warp = tid >> 5;                   // 0..7
    const int wm = warp >> 1, wn = warp & 1;
    const int grp = lane >> 2, qid = lane & 3;
    const int r0 = wm*16 + grp;                  // this thread's C rows: r0, r0+8

    const float* Qp = g_Q + (((size_t)h*B_ + b)*S_ + (size_t)qt*64)*E_;
    const float* Kp = g_K + ((size_t)h*B_ + b)*S_*E_;
    const float* Vp = g_V + (size_t)b*S_*E_;

    const int lr = tid >> 4;            // 0..15
    const int lc = (tid & 15) * 4;      // col base

    // Q: load + convert to tf32 bits ONCE (vectorized)
    #pragma unroll
    for (int t = 0; t < 4; t++) {
        int r = lr + t*16;
        float4 qv = *(const float4*)&Qp[(size_t)r*64 + lc];
        *(uint4*)&QsU[r*68 + lc] = f2tf32_v4(qv);
    }
    if (tid < 64) { m_sh[tid] = -1e30f; l_sh[tid] = 0.f; }

    // prefetch K/V tile 0
    float4 kv_pre[4], vv_pre[4];
    #pragma unroll
    for (int t = 0; t < 4; t++) {
        int r = lr + t*16;
        kv_pre[t] = *(const float4*)&Kp[(size_t)r*64 + lc];
        vv_pre[t] = *(const float4*)&Vp[(size_t)r*64 + lc];
    }

    float acc_o[4][4] = {};                      // PV accumulator (C layout)

    for (int j = 0; j <= qt; j++) {
        __syncthreads();   // prev reads done; Qs/init visible on iter 0
        #pragma unroll
        for (int t = 0; t < 4; t++) {
            int r = lr + t*16;                   // key row; lc = e base
            float4 kv = kv_pre[t];
            KtU[(lc+0)*68 + r] = f2tf32(kv.x);   // transpose + convert (scatter)
            KtU[(lc+1)*68 + r] = f2tf32(kv.y);
            KtU[(lc+2)*68 + r] = f2tf32(kv.z);
            KtU[(lc+3)*68 + r] = f2tf32(kv.w);
            *(uint4*)&VsU[r*68 + lc] = f2tf32_v4(vv_pre[t]);
        }
        // issue next tile's loads NOW; they complete during compute below
        if (j < qt) {
            #pragma unroll
            for (int t = 0; t < 4; t++) {
                int r = lr + t*16;
                kv_pre[t] = *(const float4*)&Kp[(size_t)((j+1)*64 + r)*64 + lc];
                vv_pre[t] = *(const float4*)&Vp[(size_t)((j+1)*64 + r)*64 + lc];
            }
        }
        __syncthreads();

        // ---- S = Q @ K^T via single-pass TF32 MMA ----
        float acc_s[4][4] = {};
        #pragma unroll
        for (int ks = 0; ks < 8; ks++) {
            uint32_t a0 = QsU[(r0    )*68 + ks*8 + qid    ];
            uint32_t a1 = QsU[(r0 + 8)*68 + ks*8 + qid    ];
            uint32_t a2 = QsU[(r0    )*68 + ks*8 + qid + 4];
            uint32_t a3 = QsU[(r0 + 8)*68 + ks*8 + qid + 4];
            #pragma unroll
            for (int jn = 0; jn < 4; jn++) {
                int col = wn*32 + jn*8;
                uint32_t b0 = KtU[(ks*8 + qid    )*68 + col + grp];
                uint32_t b1 = KtU[(ks*8 + qid + 4)*68 + col + grp];
                mma_tf32(acc_s[jn], a0, a1, a2, a3, b0, b1);
            }
        }
        const bool diag = (j == qt);
        #pragma unroll
        for (int jn = 0; jn < 4; jn++) {
            int c0 = wn*32 + jn*8 + qid*2;
            float v0 = acc_s[jn][0] * 0.125f;
            float v1 = acc_s[jn][1] * 0.125f;
            float v2 = acc_s[jn][2] * 0.125f;
            float v3 = acc_s[jn][3] * 0.125f;
            if (diag) {
                if (c0     > r0    ) v0 = -1e30f;
                if (c0 + 1 > r0    ) v1 = -1e30f;
                if (c0     > r0 + 8) v2 = -1e30f;
                if (c0 + 1 > r0 + 8) v3 = -1e30f;
            }
            *(float2*)&Ss[(r0    )*68 + c0] = make_float2(v0, v1);
            *(float2*)&Ss[(r0 + 8)*68 + c0] = make_float2(v2, v3);
        }
        __syncthreads();

        // ---- online softmax: 4 threads/row, vectorized; P -> tf32 bits ----
        {
            const int row  = tid >> 2;
            const int part = tid & 3;
            const int base = row*68 + part*16;
            float mold = m_sh[row];
            float4 sv[4];
            #pragma unroll
            for (int t = 0; t < 4; t++) sv[t] = *(const float4*)&Ss[base + t*4];
            float mx = -1e30f;
            #pragma unroll
            for (int t = 0; t < 4; t++) {
                mx = fmaxf(mx, fmaxf(fmaxf(sv[t].x, sv[t].y), fmaxf(sv[t].z, sv[t].w)));
            }
            mx = fmaxf(mx, __shfl_xor_sync(0xffffffffu, mx, 1));
            mx = fmaxf(mx, __shfl_xor_sync(0xffffffffu, mx, 2));
            mx = fmaxf(mx, mold);
            float sum = 0.f;
            #pragma unroll
            for (int t = 0; t < 4; t++) {
                float p0 = __expf(sv[t].x - mx);
                float p1 = __expf(sv[t].y - mx);
                float p2 = __expf(sv[t].z - mx);
                float p3 = __expf(sv[t].w - mx);
                sum += (p0 + p1) + (p2 + p3);
                *(uint4*)&SsU[base + t*4] =
                    make_uint4(f2tf32(p0), f2tf32(p1), f2tf32(p2), f2tf32(p3));
            }
            sum += __shfl_xor_sync(0xffffffffu, sum, 1);
            sum += __shfl_xor_sync(0xffffffffu, sum, 2);
            if (part == 0) {
                float corr = __expf(mold - mx);
                l_sh[row] = l_sh[row]*corr + sum;
                m_sh[row] = mx;
                c_sh[row] = corr;
            }
        }
        __syncthreads();

        // ---- O = O*corr + P @ V via single-pass TF32 MMA ----
        {
            float cA = c_sh[r0], cB = c_sh[r0 + 8];
            #pragma unroll
            for (int jn = 0; jn < 4; jn++) {
                acc_o[jn][0] *= cA; acc_o[jn][1] *= cA;
                acc_o[jn][2] *= cB; acc_o[jn][3] *= cB;
            }
            #pragma unroll
            for (int ks = 0; ks < 8; ks++) {
                uint32_t a0 = SsU[(r0    )*68 + ks*8 + qid    ];
                uint32_t a1 = SsU[(r0 + 8)*68 + ks*8 + qid    ];
                uint32_t a2 = SsU[(r0    )*68 + ks*8 + qid + 4];
                uint32_t a3 = SsU[(r0 + 8)*68 + ks*8 + qid + 4];
                #pragma unroll
                for (int jn = 0; jn < 4; jn++) {
                    int col = wn*32 + jn*8;
                    uint32_t b0 = VsU[(ks*8 + qid    )*68 + col + grp];
                    uint32_t b1 = VsU[(ks*8 + qid + 4)*68 + col + grp];
                    mma_tf32(acc_o[jn], a0, a1, a2, a3, b0, b1);
                }
            }
        }
    }
    __syncthreads();

    // ---- epilogue: MMA C layout, mean over heads via atomics ----
    {
        float invA = 1.f / (l_sh[r0    ] * (float)H_);
        float invB = 1.f / (l_sh[r0 + 8] * (float)H_);
        float* dst = &g_M[((size_t)b*S_ + qt*64)*E_];
        #pragma unroll
        for (int jn = 0; jn < 4; jn++) {
            int c0 = wn*32 + jn*8 + qid*2;
            atomicAdd(&dst[(size_t)(r0    )*E_ + c0    ], acc_o[jn][0]*invA);
            atomicAdd(&dst[(size_t)(r0    )*E_ + c0 + 1], acc_o[jn][1]*invA);
            atomicAdd(&dst[(size_t)(r0 + 8)*E_ + c0    ], acc_o[jn][2]*invB);
            atomicAdd(&dst[(size_t)(r0 + 8)*E_ + c0 + 1], acc_o[jn][3]*invB);
        }
    }
}

// ---------------------------------------------------------------------------
// Final linear: G = g_M[512,512] @ Wf[512,512], single-pass tf32 + prefetch,
// vectorized STS.128 converts.
__global__ void gemm_g_kernel(const float* __restrict__ Wf) {
    __shared__ uint32_t As[64*36];
    __shared__ uint32_t Bs[32*68];
    const int tid  = threadIdx.x;
    const int lane = tid & 31;
    const int warp = tid >> 5;
    const int wm = warp >> 1, wn = warp & 1;
    const int grp = lane >> 2, qid = lane & 3;
    const int m0 = blockIdx.x * 64, n0 = blockIdx.y * 64;

    const int ar[4] = { (tid      ) >> 3, (tid + 128) >> 3, (tid + 256) >> 3, (tid + 384) >> 3 };
    const int ac[4] = { ((tid      ) & 7)*4, ((tid + 128) & 7)*4, ((tid + 256) & 7)*4, ((tid + 384) & 7)*4 };
    const int br[4] = { (tid      ) >> 4, (tid + 128) >> 4, (tid + 256) >> 4, (tid + 384) >> 4 };
    const int bc[4] = { ((tid      ) & 15)*4, ((tid + 128) & 15)*4, ((tid + 256) & 15)*4, ((tid + 384) & 15)*4 };

    float4 a_pre[4], b_pre[4];
    #pragma unroll
    for (int t = 0; t < 4; t++) {
        a_pre[t] = *(const float4*)&g_M[(size_t)(m0 + ar[t])*512 + ac[t]];
        b_pre[t] = *(const float4*)&Wf[(size_t)br[t]*512 + n0 + bc[t]];
    }

    float acc[2][4][4] = {};

    for (int k0 = 0; k0 < 512; k0 += 32) {
        #pragma unroll
        for (int t = 0; t < 4; t++) {
            *(uint4*)&As[ar[t]*36 + ac[t]] = f2tf32_v4(a_pre[t]);
            *(uint4*)&Bs[br[t]*68 + bc[t]] = f2tf32_v4(b_pre[t]);
        }
        if (k0 + 32 < 512) {
            #pragma unroll
            for (int t = 0; t < 4; t++) {
                a_pre[t] = *(const float4*)&g_M[(size_t)(m0 + ar[t])*512 + k0 + 32 + ac[t]];
                b_pre[t] = *(const float4*)&Wf[(size_t)(k0 + 32 + br[t])*512 + n0 + bc[t]];
            }
        }
        __syncthreads();

        #pragma unroll
        for (int ks = 0; ks < 4; ks++) {
            uint32_t a[2][4];
            #pragma unroll
            for (int i = 0; i < 2; i++) {
                int row = wm*32 + i*16;
                a[i][0] = As[(row+grp  )*36 + ks*8 + qid    ];
                a[i][1] = As[(row+grp+8)*36 + ks*8 + qid    ];
                a[i][2] = As[(row+grp  )*36 + ks*8 + qid + 4];
                a[i][3] = As[(row+grp+8)*36 + ks*8 + qid + 4];
            }
            #pragma unroll
            for (int jn = 0; jn < 4; jn++) {
                int col = wn*32 + jn*8;
                uint32_t b0 = Bs[(ks*8 + qid    )*68 + col + grp];
                uint32_t b1 = Bs[(ks*8 + qid + 4)*68 + col + grp];
                mma_tf32(acc[0][jn], a[0][0], a[0][1], a[0][2], a[0][3], b0, b1);
                mma_tf32(acc[1][jn], a[1][0], a[1][1], a[1][2], a[1][3], b0, b1);
            }
        }
        __syncthreads();
    }

    #pragma unroll
    for (int i = 0; i < 2; i++) {
        int row0 = m0 + wm*32 + i*16 + grp;
        #pragma unroll
        for (int jn = 0; jn < 4; jn++) {
            int col0 = n0 + wn*32 + jn*8 + qid*2;
            g_G[(size_t)row0*512     + col0    ] = acc[i][jn][0];
            g_G[(size_t)row0*512     + col0 + 1] = acc[i][jn][1];
            g_G[(size_t)(row0+8)*512 + col0    ] = acc[i][jn][2];
            g_G[(size_t)(row0+8)*512 + col0 + 1] = acc[i][jn][3];
        }
    }
}

// ---------------------------------------------------------------------------
__global__ void ln_kernel(const float* __restrict__ query, const float* __restrict__ bf,
                          const float* __restrict__ lnw, const float* __restrict__ lnb,
                          float* __restrict__ out) {
    const int row  = blockIdx.x;
    const int bb   = row >> 10;
    const int r128 = row & 127;
    const float* g    = g_G + ((size_t)bb*128 + r128)*D_;
    const float* qrow = query + (size_t)row*D_;
    const int tid = threadIdx.x;
    float x[4];
    float sum = 0.f;
    #pragma unroll
    for (int t = 0; t < 4; t++) {
        int c = tid + t*128;
        x[t] = g[c] + bf[c] + qrow[c];
        sum += x[t];
    }
    __shared__ float red[4];
    __shared__ float red2[4];
    #pragma unroll
    for (int off = 16; off; off >>= 1) sum += __shfl_xor_sync(0xffffffffu, sum, off);
    if ((tid & 31) == 0) red[tid >> 5] = sum;
    __syncthreads();
    float mean = (red[0]+red[1]+red[2]+red[3]) * (1.f/512.f);

    float sq = 0.f;
    #pragma unroll
    for (int t = 0; t < 4; t++) { float d = x[t] - mean; sq += d*d; }
    #pragma unroll
    for (int off = 16; off; off >>= 1) sq += __shfl_xor_sync(0xffffffffu, sq, off);
    if ((tid & 31) == 0) red2[tid >> 5] = sq;
    __syncthreads();
    float var_num = red2[0]+red2[1]+red2[2]+red2[3];
    float stdv = sqrtf(var_num * (1.f/511.f));
    float inv  = 1.f / (stdv + 1e-6f);
    #pragma unroll
    for (int t = 0; t < 4; t++) {
        int c = tid + t*128;
        out[(size_t)row*D_ + c] = lnw[c]*(x[t]-mean)*inv + lnb[c];
    }
}

// ---------------------------------------------------------------------------
extern "C" void kernel_launch(void* const* d_in, const int* in_sizes, int n_in,
                              void* d_out, int out_size) {
    const float* query = (const float*)d_in[0];
    const float* key   = (const float*)d_in[1];
    const float* value = (const float*)d_in[2];
    // d_in[3] = mask (tril, handled analytically)
    const float* Wq = (const float*)d_in[4];
    const float* bq = (const float*)d_in[5];
    const float* Wk = (const float*)d_in[6];
    const float* bk = (const float*)d_in[7];
    const float* Wv = (const float*)d_in[8];
    const float* bv = (const float*)d_in[9];
    const float* Wf = (const float*)d_in[10];
    const float* bf = (const float*)d_in[11];
    const float* lnw = (const float*)d_in[12];
    const float* lnb = (const float*)d_in[13];
    float* out = (float*)d_out;

    // attn smem: 4 tiles of 64*68 + 3*64 floats = 70400 B
    const size_t attn_smem = (size_t)(4*64*68 + 3*64) * sizeof(float);
    cudaFuncSetAttribute(attn_kernel, cudaFuncAttributeMaxDynamicSharedMemorySize,
                         (int)attn_smem);

    zero_m_kernel<<<64, 256>>>();
    proj_mma_kernel<<<dim3(BS_/64, 17), 128>>>(query, key, value, Wq, bq, Wk, bk, Wv, bv);
    attn_kernel<<<dim3(S_/64, B_, H_), 256, attn_smem>>>();
    gemm_g_kernel<<<dim3(8, 8), 128>>>(Wf);
    ln_kernel<<<BS_, 128>>>(query, bf, lnw, lnb, out);
}

// round 17
// speedup vs baseline: 1.0646x; 1.0646x over previous
#include <cuda_runtime.h>
#include <math.h>
#include <stdint.h>

#define B_ 4
#define S_ 1024
#define D_ 512
#define H_ 8
#define E_ 64
#define BS_ (B_*S_)

// Scratch (device globals — no runtime allocation allowed)
__device__ float g_Q[H_*BS_*E_];     // [H][B*S][E]
__device__ float g_K[H_*BS_*E_];
__device__ float g_V[BS_*E_];
__device__ float g_M[BS_*E_];        // mean-over-heads accumulator
__device__ float g_G[B_*128*D_];     // final-GEMM output [512][512]

// ---------------------------------------------------------------------------
__device__ __forceinline__ uint32_t f2tf32(float x) {
    uint32_t r;
    asm("cvt.rna.tf32.f32 %0, %1;" : "=r"(r) : "f"(x));
    return r;
}
__device__ __forceinline__ uint4 f2tf32_v4(float4 v) {
    return make_uint4(f2tf32(v.x), f2tf32(v.y), f2tf32(v.z), f2tf32(v.w));
}

// D += A(16x8,row) * B(8x8,col)   tf32, fp32 accum
__device__ __forceinline__ void mma_tf32(float c[4],
                                         uint32_t a0, uint32_t a1, uint32_t a2, uint32_t a3,
                                         uint32_t b0, uint32_t b1) {
    asm volatile(
        "mma.sync.aligned.m16n8k8.row.col.f32.tf32.tf32.f32 "
        "{%0,%1,%2,%3}, {%4,%5,%6,%7}, {%8,%9}, {%0,%1,%2,%3};\n"
        : "+f"(c[0]), "+f"(c[1]), "+f"(c[2]), "+f"(c[3])
        : "r"(a0), "r"(a1), "r"(a2), "r"(a3), "r"(b0), "r"(b1));
}

// ---------------------------------------------------------------------------
__global__ void zero_m_kernel() {
    int i = blockIdx.x * blockDim.x + threadIdx.x;
    int stride = gridDim.x * blockDim.x;
    for (; i < BS_*E_; i += stride) g_M[i] = 0.f;
}

// ---------------------------------------------------------------------------
// Batched projections, single-pass tf32, vectorized converts, prefetch (R16).
__global__ void proj_mma_kernel(const float* __restrict__ q, const float* __restrict__ k,
                                const float* __restrict__ v,
                                const float* __restrict__ Wq, const float* __restrict__ bq,
                                const float* __restrict__ Wk, const float* __restrict__ bk,
                                const float* __restrict__ Wv, const float* __restrict__ bv) {
    const int p = blockIdx.y;
    const float* A; const float* W; const float* bias; float* out;
    if (p < 8)       { A = q; W = Wq + (size_t)p*D_*E_;     bias = bq + p*E_;     out = g_Q + (size_t)p*BS_*E_; }
    else if (p < 16) { A = k; W = Wk + (size_t)(p-8)*D_*E_; bias = bk + (p-8)*E_; out = g_K + (size_t)(p-8)*BS_*E_; }
    else             { A = v; W = Wv;                        bias = bv;            out = g_V; }

    __shared__ uint32_t As[64*36];   // [row][k]  tf32 bits
    __shared__ uint32_t Bs[32*68];   // [k][n]    tf32 bits

    const int tid  = threadIdx.x;
    const int lane = tid & 31;
    const int warp = tid >> 5;
    const int wm = warp >> 1, wn = warp & 1;
    const int grp = lane >> 2, qid = lane & 3;
    const int m0 = blockIdx.x * 64;

    const int ar[4] = { (tid      ) >> 3, (tid + 128) >> 3, (tid + 256) >> 3, (tid + 384) >> 3 };
    const int ac[4] = { ((tid      ) & 7)*4, ((tid + 128) & 7)*4, ((tid + 256) & 7)*4, ((tid + 384) & 7)*4 };
    const int br[4] = { (tid      ) >> 4, (tid + 128) >> 4, (tid + 256) >> 4, (tid + 384) >> 4 };
    const int bc[4] = { ((tid      ) & 15)*4, ((tid + 128) & 15)*4, ((tid + 256) & 15)*4, ((tid + 384) & 15)*4 };

    float4 a_pre[4], b_pre[4];
    #pragma unroll
    for (int t = 0; t < 4; t++) {
        a_pre[t] = *(const float4*)&A[(size_t)(m0 + ar[t])*D_ + ac[t]];
        b_pre[t] = *(const float4*)&W[(size_t)br[t]*E_ + bc[t]];
    }

    float acc[2][4][4] = {};

    for (int k0 = 0; k0 < D_; k0 += 32) {
        #pragma unroll
        for (int t = 0; t < 4; t++) {
            *(uint4*)&As[ar[t]*36 + ac[t]] = f2tf32_v4(a_pre[t]);
            *(uint4*)&Bs[br[t]*68 + bc[t]] = f2tf32_v4(b_pre[t]);
        }
        if (k0 + 32 < D_) {
            #pragma unroll
            for (int t = 0; t < 4; t++) {
                a_pre[t] = *(const float4*)&A[(size_t)(m0 + ar[t])*D_ + k0 + 32 + ac[t]];
                b_pre[t] = *(const float4*)&W[(size_t)(k0 + 32 + br[t])*E_ + bc[t]];
            }
        }
        __syncthreads();

        #pragma unroll
        for (int ks = 0; ks < 4; ks++) {
            uint32_t a[2][4];
            #pragma unroll
            for (int i = 0; i < 2; i++) {
                int row = wm*32 + i*16;
                a[i][0] = As[(row+grp  )*36 + ks*8 + qid    ];
                a[i][1] = As[(row+grp+8)*36 + ks*8 + qid    ];
                a[i][2] = As[(row+grp  )*36 + ks*8 + qid + 4];
                a[i][3] = As[(row+grp+8)*36 + ks*8 + qid + 4];
            }
            #pragma unroll
            for (int j = 0; j < 4; j++) {
                int col = wn*32 + j*8;
                uint32_t b0 = Bs[(ks*8 + qid    )*68 + col + grp];
                uint32_t b1 = Bs[(ks*8 + qid + 4)*68 + col + grp];
                mma_tf32(acc[0][j], a[0][0], a[0][1], a[0][2], a[0][3], b0, b1);
                mma_tf32(acc[1][j], a[1][0], a[1][1], a[1][2], a[1][3], b0, b1);
            }
        }
        __syncthreads();
    }

    #pragma unroll
    for (int i = 0; i < 2; i++) {
        int row0 = m0 + wm*32 + i*16 + grp;
        #pragma unroll
        for (int j = 0; j < 4; j++) {
            int col0 = wn*32 + j*8 + qid*2;
            out[(size_t)row0*E_     + col0    ] = acc[i][j][0] + bias[col0    ];
            out[(size_t)row0*E_     + col0 + 1] = acc[i][j][1] + bias[col0 + 1];
            out[(size_t)(row0+8)*E_ + col0    ] = acc[i][j][2] + bias[col0    ];
            out[(size_t)(row0+8)*E_ + col0 + 1] = acc[i][j][3] + bias[col0 + 1];
        }
    }
}

// ---------------------------------------------------------------------------
// Flash attention, warp-owns-full-rows (FA2 style): 128 threads, 4 warps,
// each warp = 16 q-rows x ALL 64 key-cols. Softmax fully in registers
// (quad shfl) — no score smem, no m/l/c smem, no softmax barriers.
// Block barriers only around shared K/V tiles: 2 per iteration (was 4).
// All single-pass tf32; K/V register prefetch.
__global__ void __launch_bounds__(128, 3) attn_kernel() {
    const int qt = (int)gridDim.x - 1 - (int)blockIdx.x;   // heavy first
    const int b = blockIdx.y, h = blockIdx.z;
    extern __shared__ float sm[];
    uint32_t* QsU = (uint32_t*)sm;           // 64*68 [q][e]   tf32 bits
    uint32_t* KtU = QsU + 64*68;             // 64*68 [e][key] tf32 bits
    uint32_t* VsU = KtU + 64*68;             // 64*68 [key][e] tf32 bits
    uint32_t* PsU = VsU + 64*68;             // 64*68 [q][key] P tf32 bits

    const int tid  = threadIdx.x;
    const int lane = tid & 31;
    const int warp = tid >> 5;                   // 0..3
    const int grp = lane >> 2, qid = lane & 3;
    const int r0 = warp*16 + grp;                // this thread's rows: r0, r0+8

    const float* Qp = g_Q + (((size_t)h*B_ + b)*S_ + (size_t)qt*64)*E_;
    const float* Kp = g_K + ((size_t)h*B_ + b)*S_*E_;
    const float* Vp = g_V + (size_t)b*S_*E_;

    const int lr = tid >> 4;            // 0..7
    const int lc = (tid & 15) * 4;      // col base

    // Q: load + convert ONCE (8 rows per thread)
    #pragma unroll
    for (int t = 0; t < 8; t++) {
        int r = lr + t*8;
        float4 qv = *(const float4*)&Qp[(size_t)r*64 + lc];
        *(uint4*)&QsU[r*68 + lc] = f2tf32_v4(qv);
    }

    // prefetch K/V tile 0
    float4 kv_pre[8], vv_pre[8];
    #pragma unroll
    for (int t = 0; t < 8; t++) {
        int r = lr + t*8;
        kv_pre[t] = *(const float4*)&Kp[(size_t)r*64 + lc];
        vv_pre[t] = *(const float4*)&Vp[(size_t)r*64 + lc];
    }

    float m_r0 = -1e30f, m_r1 = -1e30f;
    float l_r0 = 0.f,    l_r1 = 0.f;
    float acc_o[8][4] = {};                      // 16 rows x 64 cols (C layout)

    for (int j = 0; j <= qt; j++) {
        __syncthreads();   // prev iter's K/V reads done (Q/init visible iter 0)
        #pragma unroll
        for (int t = 0; t < 8; t++) {
            int r = lr + t*8;                    // key row; lc = e base
            float4 kv = kv_pre[t];
            KtU[(lc+0)*68 + r] = f2tf32(kv.x);   // transpose + convert (scatter)
            KtU[(lc+1)*68 + r] = f2tf32(kv.y);
            KtU[(lc+2)*68 + r] = f2tf32(kv.z);
            KtU[(lc+3)*68 + r] = f2tf32(kv.w);
            *(uint4*)&VsU[r*68 + lc] = f2tf32_v4(vv_pre[t]);
        }
        if (j < qt) {
            #pragma unroll
            for (int t = 0; t < 8; t++) {
                int r = lr + t*8;
                kv_pre[t] = *(const float4*)&Kp[(size_t)((j+1)*64 + r)*64 + lc];
                vv_pre[t] = *(const float4*)&Vp[(size_t)((j+1)*64 + r)*64 + lc];
            }
        }
        __syncthreads();

        // ---- S = Q @ K^T (this warp: rows r0/r0+8, all 8 jn col-blocks) ----
        float acc_s[8][4] = {};
        #pragma unroll
        for (int ks = 0; ks < 8; ks++) {
            uint32_t a0 = QsU[(r0    )*68 + ks*8 + qid    ];
            uint32_t a1 = QsU[(r0 + 8)*68 + ks*8 + qid    ];
            uint32_t a2 = QsU[(r0    )*68 + ks*8 + qid + 4];
            uint32_t a3 = QsU[(r0 + 8)*68 + ks*8 + qid + 4];
            #pragma unroll
            for (int jn = 0; jn < 8; jn++) {
                int col = jn*8;
                uint32_t b0 = KtU[(ks*8 + qid    )*68 + col + grp];
                uint32_t b1 = KtU[(ks*8 + qid + 4)*68 + col + grp];
                mma_tf32(acc_s[jn], a0, a1, a2, a3, b0, b1);
            }
        }

        // ---- scale + mask in registers; row max via quad shfl ----
        const bool diag = (j == qt);
        float mx0 = -1e30f, mx1 = -1e30f;
        #pragma unroll
        for (int jn = 0; jn < 8; jn++) {
            int c0 = jn*8 + qid*2;
            float v0 = acc_s[jn][0] * 0.125f;
            float v1 = acc_s[jn][1] * 0.125f;
            float v2 = acc_s[jn][2] * 0.125f;
            float v3 = acc_s[jn][3] * 0.125f;
            if (diag) {
                if (c0     > r0    ) v0 = -1e30f;
                if (c0 + 1 > r0    ) v1 = -1e30f;
                if (c0     > r0 + 8) v2 = -1e30f;
                if (c0 + 1 > r0 + 8) v3 = -1e30f;
            }
            acc_s[jn][0] = v0; acc_s[jn][1] = v1;
            acc_s[jn][2] = v2; acc_s[jn][3] = v3;
            mx0 = fmaxf(mx0, fmaxf(v0, v1));
            mx1 = fmaxf(mx1, fmaxf(v2, v3));
        }
        mx0 = fmaxf(mx0, __shfl_xor_sync(0xffffffffu, mx0, 1));
        mx0 = fmaxf(mx0, __shfl_xor_sync(0xffffffffu, mx0, 2));
        mx1 = fmaxf(mx1, __shfl_xor_sync(0xffffffffu, mx1, 1));
        mx1 = fmaxf(mx1, __shfl_xor_sync(0xffffffffu, mx1, 2));
        mx0 = fmaxf(mx0, m_r0);
        mx1 = fmaxf(mx1, m_r1);

        // ---- exp + row sum in registers; P -> tf32 bits in smem ----
        float corr0 = __expf(m_r0 - mx0);
        float corr1 = __expf(m_r1 - mx1);
        float sum0 = 0.f, sum1 = 0.f;
        #pragma unroll
        for (int jn = 0; jn < 8; jn++) {
            int c0 = jn*8 + qid*2;
            float p0 = __expf(acc_s[jn][0] - mx0);
            float p1 = __expf(acc_s[jn][1] - mx0);
            float p2 = __expf(acc_s[jn][2] - mx1);
            float p3 = __expf(acc_s[jn][3] - mx1);
            sum0 += p0 + p1;
            sum1 += p2 + p3;
            *(uint2*)&PsU[(r0    )*68 + c0] = make_uint2(f2tf32(p0), f2tf32(p1));
            *(uint2*)&PsU[(r0 + 8)*68 + c0] = make_uint2(f2tf32(p2), f2tf32(p3));
        }
        sum0 += __shfl_xor_sync(0xffffffffu, sum0, 1);
        sum0 += __shfl_xor_sync(0xffffffffu, sum0, 2);
        sum1 += __shfl_xor_sync(0xffffffffu, sum1, 1);
        sum1 += __shfl_xor_sync(0xffffffffu, sum1, 2);
        l_r0 = l_r0*corr0 + sum0;  m_r0 = mx0;
        l_r1 = l_r1*corr1 + sum1;  m_r1 = mx1;

        #pragma unroll
        for (int jn = 0; jn < 8; jn++) {
            acc_o[jn][0] *= corr0; acc_o[jn][1] *= corr0;
            acc_o[jn][2] *= corr1; acc_o[jn][3] *= corr1;
        }
        __syncwarp();   // P rows are warp-private: warp sync suffices

        // ---- O += P @ V ----
        #pragma unroll
        for (int ks = 0; ks < 8; ks++) {
            uint32_t a0 = PsU[(r0    )*68 + ks*8 + qid    ];
            uint32_t a1 = PsU[(r0 + 8)*68 + ks*8 + qid    ];
            uint32_t a2 = PsU[(r0    )*68 + ks*8 + qid + 4];
            uint32_t a3 = PsU[(r0 + 8)*68 + ks*8 + qid + 4];
            #pragma unroll
            for (int jn = 0; jn < 8; jn++) {
                int col = jn*8;
                uint32_t b0 = VsU[(ks*8 + qid    )*68 + col + grp];
                uint32_t b1 = VsU[(ks*8 + qid + 4)*68 + col + grp];
                mma_tf32(acc_o[jn], a0, a1, a2, a3, b0, b1);
            }
        }
    }

    // ---- epilogue: mean over heads via atomics ----
    {
        float invA = 1.f / (l_r0 * (float)H_);
        float invB = 1.f / (l_r1 * (float)H_);
        float* dst = &g_M[((size_t)b*S_ + qt*64)*E_];
        #pragma unroll
        for (int jn = 0; jn < 8; jn++) {
            int c0 = jn*8 + qid*2;
            atomicAdd(&dst[(size_t)(r0    )*E_ + c0    ], acc_o[jn][0]*invA);
            atomicAdd(&dst[(size_t)(r0    )*E_ + c0 + 1], acc_o[jn][1]*invA);
            atomicAdd(&dst[(size_t)(r0 + 8)*E_ + c0    ], acc_o[jn][2]*invB);
            atomicAdd(&dst[(size_t)(r0 + 8)*E_ + c0 + 1], acc_o[jn][3]*invB);
        }
    }
}

// ---------------------------------------------------------------------------
// Final linear: G = g_M[512,512] @ Wf[512,512], single-pass tf32 + prefetch.
__global__ void gemm_g_kernel(const float* __restrict__ Wf) {
    __shared__ uint32_t As[64*36];
    __shared__ uint32_t Bs[32*68];
    const int tid  = threadIdx.x;
    const int lane = tid & 31;
    const int warp = tid >> 5;
    const int wm = warp >> 1, wn = warp & 1;
    const int grp = lane >> 2, qid = lane & 3;
    const int m0 = blockIdx.x * 64, n0 = blockIdx.y * 64;

    const int ar[4] = { (tid      ) >> 3, (tid + 128) >> 3, (tid + 256) >> 3, (tid + 384) >> 3 };
    const int ac[4] = { ((tid      ) & 7)*4, ((tid + 128) & 7)*4, ((tid + 256) & 7)*4, ((tid + 384) & 7)*4 };
    const int br[4] = { (tid      ) >> 4, (tid + 128) >> 4, (tid + 256) >> 4, (tid + 384) >> 4 };
    const int bc[4] = { ((tid      ) & 15)*4, ((tid + 128) & 15)*4, ((tid + 256) & 15)*4, ((tid + 384) & 15)*4 };

    float4 a_pre[4], b_pre[4];
    #pragma unroll
    for (int t = 0; t < 4; t++) {
        a_pre[t] = *(const float4*)&g_M[(size_t)(m0 + ar[t])*512 + ac[t]];
        b_pre[t] = *(const float4*)&Wf[(size_t)br[t]*512 + n0 + bc[t]];
    }

    float acc[2][4][4] = {};

    for (int k0 = 0; k0 < 512; k0 += 32) {
        #pragma unroll
        for (int t = 0; t < 4; t++) {
            *(uint4*)&As[ar[t]*36 + ac[t]] = f2tf32_v4(a_pre[t]);
            *(uint4*)&Bs[br[t]*68 + bc[t]] = f2tf32_v4(b_pre[t]);
        }
        if (k0 + 32 < 512) {
            #pragma unroll
            for (int t = 0; t < 4; t++) {
                a_pre[t] = *(const float4*)&g_M[(size_t)(m0 + ar[t])*512 + k0 + 32 + ac[t]];
                b_pre[t] = *(const float4*)&Wf[(size_t)(k0 + 32 + br[t])*512 + n0 + bc[t]];
            }
        }
        __syncthreads();

        #pragma unroll
        for (int ks = 0; ks < 4; ks++) {
            uint32_t a[2][4];
            #pragma unroll
            for (int i = 0; i < 2; i++) {
                int row = wm*32 + i*16;
                a[i][0] = As[(row+grp  )*36 + ks*8 + qid    ];
                a[i][1] = As[(row+grp+8)*36 + ks*8 + qid    ];
                a[i][2] = As[(row+grp  )*36 + ks*8 + qid + 4];
                a[i][3] = As[(row+grp+8)*36 + ks*8 + qid + 4];
            }
            #pragma unroll
            for (int jn = 0; jn < 4; jn++) {
                int col = wn*32 + jn*8;
                uint32_t b0 = Bs[(ks*8 + qid    )*68 + col + grp];
                uint32_t b1 = Bs[(ks*8 + qid + 4)*68 + col + grp];
                mma_tf32(acc[0][jn], a[0][0], a[0][1], a[0][2], a[0][3], b0, b1);
                mma_tf32(acc[1][jn], a[1][0], a[1][1], a[1][2], a[1][3], b0, b1);
            }
        }
        __syncthreads();
    }

    #pragma unroll
    for (int i = 0; i < 2; i++) {
        int row0 = m0 + wm*32 + i*16 + grp;
        #pragma unroll
        for (int jn = 0; jn < 4; jn++) {
            int col0 = n0 + wn*32 + jn*8 + qid*2;
            g_G[(size_t)row0*512     + col0    ] = acc[i][jn][0];
            g_G[(size_t)row0*512     + col0 + 1] = acc[i][jn][1];
            g_G[(size_t)(row0+8)*512 + col0    ] = acc[i][jn][2];
            g_G[(size_t)(row0+8)*512 + col0 + 1] = acc[i][jn][3];
        }
    }
}

// ---------------------------------------------------------------------------
__global__ void ln_kernel(const float* __restrict__ query, const float* __restrict__ bf,
                          const float* __restrict__ lnw, const float* __restrict__ lnb,
                          float* __restrict__ out) {
    const int row  = blockIdx.x;
    const int bb   = row >> 10;
    const int r128 = row & 127;
    const float* g    = g_G + ((size_t)bb*128 + r128)*D_;
    const float* qrow = query + (size_t)row*D_;
    const int tid = threadIdx.x;
    float x[4];
    float sum = 0.f;
    #pragma unroll
    for (int t = 0; t < 4; t++) {
        int c = tid + t*128;
        x[t] = g[c] + bf[c] + qrow[c];
        sum += x[t];
    }
    __shared__ float red[4];
    __shared__ float red2[4];
    #pragma unroll
    for (int off = 16; off; off >>= 1) sum += __shfl_xor_sync(0xffffffffu, sum, off);
    if ((tid & 31) == 0) red[tid >> 5] = sum;
    __syncthreads();
    float mean = (red[0]+red[1]+red[2]+red[3]) * (1.f/512.f);

    float sq = 0.f;
    #pragma unroll
    for (int t = 0; t < 4; t++) { float d = x[t] - mean; sq += d*d; }
    #pragma unroll
    for (int off = 16; off; off >>= 1) sq += __shfl_xor_sync(0xffffffffu, sq, off);
    if ((tid & 31) == 0) red2[tid >> 5] = sq;
    __syncthreads();
    float var_num = red2[0]+red2[1]+red2[2]+red2[3];
    float stdv = sqrtf(var_num * (1.f/511.f));
    float inv  = 1.f / (stdv + 1e-6f);
    #pragma unroll
    for (int t = 0; t < 4; t++) {
        int c = tid + t*128;
        out[(size_t)row*D_ + c] = lnw[c]*(x[t]-mean)*inv + lnb[c];
    }
}

// ---------------------------------------------------------------------------
extern "C" void kernel_launch(void* const* d_in, const int* in_sizes, int n_in,
                              void* d_out, int out_size) {
    const float* query = (const float*)d_in[0];
    const float* key   = (const float*)d_in[1];
    const float* value = (const float*)d_in[2];
    // d_in[3] = mask (tril, handled analytically)
    const float* Wq = (const float*)d_in[4];
    const float* bq = (const float*)d_in[5];
    const float* Wk = (const float*)d_in[6];
    const float* bk = (const float*)d_in[7];
    const float* Wv = (const float*)d_in[8];
    const float* bv = (const float*)d_in[9];
    const float* Wf = (const float*)d_in[10];
    const float* bf = (const float*)d_in[11];
    const float* lnw = (const float*)d_in[12];
    const float* lnb = (const float*)d_in[13];
    float* out = (float*)d_out;

    // attn smem: 4 tiles of 64*68 uint32 = 69632 B
    const size_t attn_smem = (size_t)(4*64*68) * sizeof(uint32_t);
    cudaFuncSetAttribute(attn_kernel, cudaFuncAttributeMaxDynamicSharedMemorySize,
                         (int)attn_smem);

    zero_m_kernel<<<64, 256>>>();
    proj_mma_kernel<<<dim3(BS_/64, 17), 128>>>(query, key, value, Wq, bq, Wk, bk, Wv, bv);
    attn_kernel<<<dim3(S_/64, B_, H_), 128, attn_smem>>>();
    gemm_g_kernel<<<dim3(8, 8), 128>>>(Wf);
    ln_kernel<<<BS_, 128>>>(query, bf, lnw, lnb, out);
}